// round 14
// baseline (speedup 1.0000x reference)
#include <cuda_runtime.h>
#include <cstdint>

#define KD     24000   // inner (pooled-over) dimension
#define NCH    32      // feature channels
#define RPW    8       // rows per warp
#define NROWS  12000
#define KSPLIT 2
#define HALFK  (KD / KSPLIT)        // 12000 k's per warp
#define KB     96                   // k-chunk staged in smem (12000 = 125 * 96)
#define KBP    112                  // padded row stride: conflict-free STS.128
#define NCHUNK_H (HALFK / KB)       // 125
#define NSTEP  (KB / 4)             // 24 4-k steps per chunk
#define F4L    ((RPW * KB) / (4 * 32))   // 6 float4 R-loads per lane per chunk

typedef unsigned long long ull;

// k-split partial results (written fully every launch; no zeroing needed)
__device__ float g_part[KSPLIT][NROWS * NCH];
__device__ float g_rsum[KSPLIT][NROWS];

__device__ __forceinline__ ull pack2(float lo, float hi) {
    ull r;
    asm("mov.b64 %0, {%1, %2};" : "=l"(r) : "f"(lo), "f"(hi));
    return r;
}
__device__ __forceinline__ void unpack2(ull v, float& lo, float& hi) {
    asm("mov.b64 {%0, %1}, %2;" : "=f"(lo), "=f"(hi) : "l"(v));
}
__device__ __forceinline__ void fma2(ull& d, ull a, ull b) {
    asm("fma.rn.f32x2 %0, %1, %2, %0;" : "+l"(d) : "l"(a), "l"(b));
}
__device__ __forceinline__ void add2(ull& d, ull a) {
    asm("add.rn.f32x2 %0, %0, %1;" : "+l"(d) : "l"(a));
}

// 3000 CTAs -> ~21 co-resident CTAs/SM (5+ warps/SMSP) for latency hiding.
__global__ __launch_bounds__(32, 21)
void meshpool_partial(const float* __restrict__ F,   // [KD][NCH]
                      const float* __restrict__ R)   // [NROWS][KD]
{
    __shared__ float stage[2][RPW][KBP];

    const int lane = threadIdx.x & 31;
    const int row0 = blockIdx.x * RPW;
    const int half = blockIdx.y;               // k-split index
    const int base_k = half * HALFK;

    const int subrow = lane >> 2;    // 0..7 : which of this warp's rows I stage
    const int quad   = lane & 3;     // 0..3 : float4 slot within 64B group

    const float* rptr = R + (size_t)(row0 + subrow) * KD + base_k + quad * 4;
    const float* fbase = F + (size_t)base_k * NCH + lane;

    ull acc[RPW];
#pragma unroll
    for (int r = 0; r < RPW; r++) acc[r] = 0ULL;
    ull sp0 = 0ULL, sp1 = 0ULL;

    // R prefetch (chunk 0), streaming: use-once
    float4 buf[F4L];
#pragma unroll
    for (int j = 0; j < F4L; j++)
        buf[j] = __ldcs((const float4*)(rptr + j * 16));

    // ---- F software pipeline, 3 steps deep, contiguous across chunks ----
    // global step g covers k = base_k + 4g; address = fbase + g*4*NCH.
    ull fa[3], fb[3];
#pragma unroll
    for (int p = 0; p < 3; p++) {
        const float* fq = fbase + (size_t)p * 4 * NCH;
        float f0 = __ldg(fq + 0 * NCH);
        float f1 = __ldg(fq + 1 * NCH);
        float f2 = __ldg(fq + 2 * NCH);
        float f3 = __ldg(fq + 3 * NCH);
        fa[p] = pack2(f0, f1);
        fb[p] = pack2(f2, f3);
    }

    for (int c = 0; c < NCHUNK_H; c++) {
        float (*st)[KBP] = stage[c & 1];

        // stage R chunk c + rowsum partials (lane-distinct data)
#pragma unroll
        for (int j = 0; j < F4L; j++) {
            *(float4*)&st[subrow][quad * 4 + j * 16] = buf[j];
            add2(sp0, pack2(buf[j].x, buf[j].y));
            add2(sp1, pack2(buf[j].z, buf[j].w));
        }

        // prefetch R chunk c+1 (a full chunk of lookahead)
        if (c + 1 < NCHUNK_H) {
            const float* rnext = rptr + (size_t)(c + 1) * KB;
#pragma unroll
            for (int j = 0; j < F4L; j++)
                buf[j] = __ldcs((const float4*)(rnext + j * 16));
        }

        __syncwarp();

        const float* fc = fbase + (size_t)c * KB * NCH;
        const bool notlast = (c + 1 < NCHUNK_H);

#pragma unroll
        for (int s = 0; s < NSTEP; s++) {
            const int kk = s * 4;
            const int slot = s % 3;            // compile-time under full unroll
            ull fab = fa[slot];
            ull fcd = fb[slot];
#pragma unroll
            for (int r = 0; r < RPW; r++) {
                ulonglong2 rr = *(const ulonglong2*)&st[r][kk];
                fma2(acc[r], rr.x, fab);
                fma2(acc[r], rr.y, fcd);
            }
            // refill slot with step s+3 (flows into next chunk: F is k-contiguous)
            if (s < NSTEP - 3 || notlast) {
                const float* fq = fc + (size_t)(s + 3) * 4 * NCH;
                float f0 = __ldg(fq + 0 * NCH);
                float f1 = __ldg(fq + 1 * NCH);
                float f2 = __ldg(fq + 2 * NCH);
                float f3 = __ldg(fq + 3 * NCH);
                fa[slot] = pack2(f0, f1);
                fb[slot] = pack2(f2, f3);
            }
        }
    }

    // rowsum partial: lanes 4r..4r+3 hold partials of row r
    float s;
    {
        float lo0, hi0, lo1, hi1;
        unpack2(sp0, lo0, hi0);
        unpack2(sp1, lo1, hi1);
        s = (lo0 + hi0) + (lo1 + hi1);
    }
    s += __shfl_xor_sync(0xffffffffu, s, 1);
    s += __shfl_xor_sync(0xffffffffu, s, 2);
    if (quad == 0)
        g_rsum[half][row0 + subrow] = s;

    // unnormalized partial sums, coalesced 128B per row
#pragma unroll
    for (int r = 0; r < RPW; r++) {
        float lo, hi;
        unpack2(acc[r], lo, hi);
        g_part[half][(row0 + r) * NCH + lane] = lo + hi;
    }
}

__global__ __launch_bounds__(256)
void meshpool_finalize(float* __restrict__ out)
{
    int i = blockIdx.x * 256 + threadIdx.x;   // 0 .. NROWS*NCH-1
    int row = i >> 5;
    float p = g_part[0][i] + g_part[1][i];
    float rs = g_rsum[0][row] + g_rsum[1][row];
    out[i] = p / rs;
}

extern "C" void kernel_launch(void* const* d_in, const int* in_sizes, int n_in,
                              void* d_out, int out_size) {
    const float* F;
    const float* R;
    if (in_sizes[0] == KD * NCH) {
        F = (const float*)d_in[0];
        R = (const float*)d_in[1];
    } else {
        F = (const float*)d_in[1];
        R = (const float*)d_in[0];
    }
    float* out = (float*)d_out;

    // R9 post-mortem: 803us with occ 10 warps/SM -> long-scoreboard on F
    // (L2-hit ~234cyc exposed each 4-k step). Fix: k-split x2 (20+ warps/SM)
    // + 3-deep continuous F register pipeline. NEVER re-add the MaxL1
    // carveout hint (R5: 1 CTA/SM, 12.65ms).

    dim3 grid(NROWS / RPW, KSPLIT);           // (1500, 2)
    meshpool_partial<<<grid, 32>>>(F, R);
    meshpool_finalize<<<(NROWS * NCH) / 256, 256>>>(out);
}